// round 8
// baseline (speedup 1.0000x reference)
#include <cuda_runtime.h>
#include <cstdint>
#include <cstddef>

#define T_SEQ   12
#define BATCH   2048
#define IN_DIM  512
#define HIDDEN  1024

// ---------------- scratch (no runtime allocation allowed) ----------------
__device__ float d_H [BATCH * HIDDEN];                       // current hidden state
__device__ float d_RH[BATCH * HIDDEN];                       // r * h
__device__ float d_U [BATCH * HIDDEN];                       // update gate
__device__ float d_Gx[(size_t)BATCH * T_SEQ * 2 * HIDDEN];   // x@Wg_x + bg
__device__ float d_Cx[(size_t)BATCH * T_SEQ * HIDDEN];       // x@Wc_x + bc

// ---------------- mma / cp.async helpers ----------------
__device__ __forceinline__ void mma_tf32(float c[4], const uint32_t a[4], const uint32_t b[2]) {
    asm volatile(
        "mma.sync.aligned.m16n8k8.row.col.f32.tf32.tf32.f32 "
        "{%0,%1,%2,%3}, {%4,%5,%6,%7}, {%8,%9}, {%0,%1,%2,%3};\n"
        : "+f"(c[0]), "+f"(c[1]), "+f"(c[2]), "+f"(c[3])
        : "r"(a[0]), "r"(a[1]), "r"(a[2]), "r"(a[3]), "r"(b[0]), "r"(b[1]));
}

__device__ __forceinline__ void cp_async16(uint32_t dst, const void* src) {
    asm volatile("cp.async.cg.shared.global [%0], [%1], 16;\n" :: "r"(dst), "l"(src));
}

// ---------------- shared GEMM core: 128x128 block tile, BK=32, 256 threads ----------------
// 8 warps as 2 (M) x 4 (N); warp tile 64x32; 4x4 m16n8k8 mma tiles.
// 3-stage cp.async ring, ONE barrier per K-slab. Raw fp32 bits fed to tf32 MMA.
#define BM 128
#define BN 128
#define BK 32
#define NSTAGE 3
#define SA_STRIDE 36   // BK + 4
#define SB_STRIDE 136  // BN + 8
#define SA_ELEMS  (BM * SA_STRIDE)
#define SB_ELEMS  (BK * SB_STRIDE)
#define STAGE_ELEMS (SA_ELEMS + SB_ELEMS)
#define SMEM_BYTES (NSTAGE * STAGE_ELEMS * 4)   // 107520

__device__ __forceinline__ void load_stage(
    uint32_t stage_addr,
    const float* __restrict__ A, int lda,
    const float* __restrict__ B, int ldb,
    int block_row, int block_col, int k0, int tid)
{
    const uint32_t sA_addr = stage_addr;
    const uint32_t sB_addr = stage_addr + SA_ELEMS * 4;
#pragma unroll
    for (int i = 0; i < 4; i++) {
        int idx = tid + i * 256;
        int r = idx >> 3, c = (idx & 7) << 2;
        cp_async16(sA_addr + (uint32_t)(r * SA_STRIDE + c) * 4,
                   A + (size_t)(block_row + r) * lda + k0 + c);
    }
#pragma unroll
    for (int i = 0; i < 4; i++) {
        int idx = tid + i * 256;
        int r = idx >> 5, c = (idx & 31) << 2;
        cp_async16(sB_addr + (uint32_t)(r * SB_STRIDE + c) * 4,
                   B + (size_t)(k0 + r) * ldb + block_col + c);
    }
    asm volatile("cp.async.commit_group;\n" ::: "memory");
}

__device__ __forceinline__ void gemm_core(
    const float* __restrict__ A, int lda,
    const float* __restrict__ B, int ldb,
    int K, int block_row, int block_col,
    float acc[4][4][4])
{
    extern __shared__ uint32_t smem[];

    const int tid  = threadIdx.x;
    const int lane = tid & 31;
    const int warp = tid >> 5;
    const int wm   = warp & 1;
    const int wn   = warp >> 1;

    const uint32_t smem_base = (uint32_t)__cvta_generic_to_shared(smem);

#pragma unroll
    for (int mi = 0; mi < 4; mi++)
#pragma unroll
        for (int ni = 0; ni < 4; ni++)
#pragma unroll
            for (int r = 0; r < 4; r++) acc[mi][ni][r] = 0.0f;

    const int nsteps = K / BK;

    // prologue: stages 0 and 1 in flight
    load_stage(smem_base, A, lda, B, ldb, block_row, block_col, 0, tid);
    load_stage(smem_base + STAGE_ELEMS * 4, A, lda, B, ldb, block_row, block_col, BK, tid);

    int mbuf = 0;      // stage consumed this iteration  (s % 3)
    int lbuf = 2;      // stage loaded this iteration    ((s+2) % 3)

    for (int s = 0; s < nsteps; s++) {
        if (s == nsteps - 1)
            asm volatile("cp.async.wait_group 0;\n" ::: "memory");
        else
            asm volatile("cp.async.wait_group 1;\n" ::: "memory");
        __syncthreads();   // all warps done with stage (s-1); stage s visible

        if (s + 2 < nsteps) {
            load_stage(smem_base + (uint32_t)lbuf * STAGE_ELEMS * 4,
                       A, lda, B, ldb, block_row, block_col, (s + 2) * BK, tid);
        }
        lbuf = (lbuf == NSTAGE - 1) ? 0 : lbuf + 1;

        const uint32_t* cA = smem + (size_t)mbuf * STAGE_ELEMS;
        const uint32_t* cB = cA + SA_ELEMS;
        mbuf = (mbuf == NSTAGE - 1) ? 0 : mbuf + 1;

#pragma unroll
        for (int ks = 0; ks < 4; ks++) {
            const int kk = ks * 8;
            uint32_t af[4][4], bf[4][2];
#pragma unroll
            for (int mi = 0; mi < 4; mi++) {
                int rb = wm * 64 + mi * 16 + (lane >> 2);
                const uint32_t* p = cA + rb * SA_STRIDE + kk + (lane & 3);
                af[mi][0] = p[0];
                af[mi][1] = p[8 * SA_STRIDE];
                af[mi][2] = p[4];
                af[mi][3] = p[8 * SA_STRIDE + 4];
            }
#pragma unroll
            for (int ni = 0; ni < 4; ni++) {
                int cb = wn * 32 + ni * 8 + (lane >> 2);
                const uint32_t* p = cB + (kk + (lane & 3)) * SB_STRIDE + cb;
                bf[ni][0] = p[0];
                bf[ni][1] = p[4 * SB_STRIDE];
            }
#pragma unroll
            for (int mi = 0; mi < 4; mi++)
#pragma unroll
                for (int ni = 0; ni < 4; ni++)
                    mma_tf32(acc[mi][ni], af[mi], bf[ni]);
        }
        // no trailing barrier: next iteration's load targets a buffer that is
        // provably idle once all warps pass the barrier above (3-stage ring)
    }
}

#define EPI_COORDS()                                          \
    const int lane = threadIdx.x & 31;                        \
    const int warp = threadIdx.x >> 5;                        \
    const int wm = warp & 1, wn = warp >> 1;                  \
    const int block_row = blockIdx.y * BM;

__device__ __forceinline__ float sigmoidf_(float x) { return 1.0f / (1.0f + expf(-x)); }

// ---------------- kernel: h <- coded_cords ----------------
__global__ __launch_bounds__(256) void init_h_kernel(const float* __restrict__ src) {
    size_t i = (size_t)blockIdx.x * 256 + threadIdx.x;
    ((float4*)d_H)[i] = ((const float4*)src)[i];
}

// ---------------- fused gate kernel ----------------
// blocks with blockIdx.x <  nx : gate step t  = sigmoid(Gx_t + H @ Wg_h) -> RH, U
// blocks with blockIdx.x >= nx : precompute Gx chunk for t+1 = x_{t+1} @ Wg_x + bg
__global__ __launch_bounds__(256) void gate_fused_kernel(
    const float* __restrict__ x, const float* __restrict__ Wg,
    const float* __restrict__ bg, int t, int nx)
{
    float acc[4][4][4];
    EPI_COORDS();

    if ((int)blockIdx.x < nx) {
        const int block_col = blockIdx.x * BN;
        gemm_core(d_H, HIDDEN, Wg + (size_t)IN_DIM * 2 * HIDDEN, 2 * HIDDEN, HIDDEN,
                  block_row, block_col, acc);
        const bool is_reset = (block_col < HIDDEN);   // uniform per block
#pragma unroll
        for (int mi = 0; mi < 4; mi++)
#pragma unroll
            for (int ni = 0; ni < 4; ni++) {
                int row0 = block_row + wm * 64 + mi * 16 + (lane >> 2);
                int col  = block_col + wn * 32 + ni * 8 + ((lane & 3) << 1);
#pragma unroll
                for (int p = 0; p < 2; p++) {
                    int row = row0 + p * 8;
                    float2 gx = *(const float2*)&d_Gx[(size_t)(row * T_SEQ + t) * (2 * HIDDEN) + col];
                    float g0 = sigmoidf_(acc[mi][ni][2 * p + 0] + gx.x);
                    float g1 = sigmoidf_(acc[mi][ni][2 * p + 1] + gx.y);
                    if (is_reset) {
                        size_t hi = (size_t)row * HIDDEN + col;
                        float2 h = *(const float2*)&d_H[hi];
                        *(float2*)&d_RH[hi] = make_float2(g0 * h.x, g1 * h.y);
                    } else {
                        size_t ui = (size_t)row * HIDDEN + (col - HIDDEN);
                        *(float2*)&d_U[ui] = make_float2(g0, g1);
                    }
                }
            }
    } else {
        const int block_col = (blockIdx.x - nx) * BN;
        const int tt = t + 1;
        gemm_core(x + (size_t)tt * IN_DIM, T_SEQ * IN_DIM, Wg, 2 * HIDDEN, IN_DIM,
                  block_row, block_col, acc);
#pragma unroll
        for (int mi = 0; mi < 4; mi++)
#pragma unroll
            for (int ni = 0; ni < 4; ni++) {
                int row = block_row + wm * 64 + mi * 16 + (lane >> 2);
                int col = block_col + wn * 32 + ni * 8 + ((lane & 3) << 1);
                float b0 = bg[col], b1 = bg[col + 1];
                *(float2*)&d_Gx[(size_t)(row * T_SEQ + tt) * (2 * HIDDEN) + col] =
                    make_float2(acc[mi][ni][0] + b0, acc[mi][ni][1] + b1);
                *(float2*)&d_Gx[(size_t)((row + 8) * T_SEQ + tt) * (2 * HIDDEN) + col] =
                    make_float2(acc[mi][ni][2] + b0, acc[mi][ni][3] + b1);
            }
    }
}

// ---------------- fused cand kernel ----------------
// blocks with blockIdx.x <  nx : cand step t  = tanh(Cx_t + RH @ Wc_h); h = u*h+(1-u)*c
// blocks with blockIdx.x >= nx : precompute Cx chunk for t+1 = x_{t+1} @ Wc_x + bc
__global__ __launch_bounds__(256) void cand_fused_kernel(
    const float* __restrict__ x, const float* __restrict__ Wc,
    const float* __restrict__ bc, float* __restrict__ y, int t, int nx)
{
    float acc[4][4][4];
    EPI_COORDS();

    if ((int)blockIdx.x < nx) {
        const int block_col = blockIdx.x * BN;
        gemm_core(d_RH, HIDDEN, Wc + (size_t)IN_DIM * HIDDEN, HIDDEN, HIDDEN,
                  block_row, block_col, acc);
#pragma unroll
        for (int mi = 0; mi < 4; mi++)
#pragma unroll
            for (int ni = 0; ni < 4; ni++) {
                int row0 = block_row + wm * 64 + mi * 16 + (lane >> 2);
                int col  = block_col + wn * 32 + ni * 8 + ((lane & 3) << 1);
#pragma unroll
                for (int p = 0; p < 2; p++) {
                    int row = row0 + p * 8;
                    size_t hi = (size_t)row * HIDDEN + col;
                    float2 cx = *(const float2*)&d_Cx[(size_t)(row * T_SEQ + t) * HIDDEN + col];
                    float c0 = tanhf(acc[mi][ni][2 * p + 0] + cx.x);
                    float c1 = tanhf(acc[mi][ni][2 * p + 1] + cx.y);
                    float2 u = *(const float2*)&d_U[hi];
                    float2 h = *(const float2*)&d_H[hi];
                    float hn0 = u.x * h.x + (1.0f - u.x) * c0;
                    float hn1 = u.y * h.y + (1.0f - u.y) * c1;
                    *(float2*)&d_H[hi] = make_float2(hn0, hn1);
                    *(float2*)&y[(size_t)row * T_SEQ * HIDDEN + (size_t)t * HIDDEN + col] =
                        make_float2(hn0, hn1);
                }
            }
    } else {
        const int block_col = (blockIdx.x - nx) * BN;
        const int tt = t + 1;
        gemm_core(x + (size_t)tt * IN_DIM, T_SEQ * IN_DIM, Wc, HIDDEN, IN_DIM,
                  block_row, block_col, acc);
#pragma unroll
        for (int mi = 0; mi < 4; mi++)
#pragma unroll
            for (int ni = 0; ni < 4; ni++) {
                int row = block_row + wm * 64 + mi * 16 + (lane >> 2);
                int col = block_col + wn * 32 + ni * 8 + ((lane & 3) << 1);
                float b0 = bc[col], b1 = bc[col + 1];
                *(float2*)&d_Cx[(size_t)(row * T_SEQ + tt) * HIDDEN + col] =
                    make_float2(acc[mi][ni][0] + b0, acc[mi][ni][1] + b1);
                *(float2*)&d_Cx[(size_t)((row + 8) * T_SEQ + tt) * HIDDEN + col] =
                    make_float2(acc[mi][ni][2] + b0, acc[mi][ni][3] + b1);
            }
    }
}

// ---------------- launch ----------------
extern "C" void kernel_launch(void* const* d_in, const int* in_sizes, int n_in,
                              void* d_out, int out_size)
{
    const float* x  = (const float*)d_in[0];  // [B, T, D]
    const float* h0 = (const float*)d_in[1];  // [B, H]
    const float* Wg = (const float*)d_in[2];  // [D+H, 2H]
    const float* bg = (const float*)d_in[3];  // [2H]
    const float* Wc = (const float*)d_in[4];  // [D+H, H]
    const float* bc = (const float*)d_in[5];  // [H]
    float* y = (float*)d_out;                 // [B, T, H]

    cudaFuncSetAttribute(gate_fused_kernel, cudaFuncAttributeMaxDynamicSharedMemorySize, SMEM_BYTES);
    cudaFuncSetAttribute(cand_fused_kernel, cudaFuncAttributeMaxDynamicSharedMemorySize, SMEM_BYTES);

    // h <- coded_cords
    init_h_kernel<<<(BATCH * HIDDEN / 4) / 256, 256>>>(h0);

    const int NXG = 2 * HIDDEN / BN;   // 16 gate-step col blocks
    const int NXC = HIDDEN / BN;       // 8  cand-step col blocks
    const int MY  = BATCH / BM;        // 16 row blocks

    // prologue: precompute chunk t=0 only (nx=0 -> all blocks are pre-role, tt=0)
    gate_fused_kernel<<<dim3(NXG, MY), 256, SMEM_BYTES>>>(x, Wg, bg, -1, 0);
    cand_fused_kernel<<<dim3(NXC, MY), 256, SMEM_BYTES>>>(x, Wc, bc, y, -1, 0);

    // serial recurrence; each step also precomputes chunk t+1 in its spare blocks
    for (int t = 0; t < T_SEQ; t++) {
        int gx = NXG + (t < T_SEQ - 1 ? NXG : 0);
        gate_fused_kernel<<<dim3(gx, MY), 256, SMEM_BYTES>>>(x, Wg, bg, t, NXG);
        int cx = NXC + (t < T_SEQ - 1 ? NXC : 0);
        cand_fused_kernel<<<dim3(cx, MY), 256, SMEM_BYTES>>>(x, Wc, bc, y, t, NXC);
    }
}